// round 2
// baseline (speedup 1.0000x reference)
#include <cuda_runtime.h>
#include <cuda_fp16.h>
#include <cstdint>

// ---------------------------------------------------------------------------
// Problem shape (fixed by reference setup_inputs): B=4, L=4096, H=1024, F=4096
// ---------------------------------------------------------------------------
static constexpr int M_TOT = 16384;
static constexpr int H_DIM = 1024;
static constexpr int F_DIM = 4096;

// fp16 scratch (device globals: the sanctioned allocation-free scratch)
__device__ __align__(16) __half g_xh [(size_t)M_TOT * H_DIM];  // x    fp16 [M, H]
__device__ __align__(16) __half g_w1t[(size_t)F_DIM * H_DIM];  // W1^T fp16 [F, H] (K-major)
__device__ __align__(16) __half g_w2t[(size_t)H_DIM * F_DIM];  // W2^T fp16 [H, F]
__device__ __align__(16) __half g_h  [(size_t)M_TOT * F_DIM];  // relu(xW1+b1) fp16 [M, F]

// ---------------------------------------------------------------------------
// PTX helpers — ONLY portable sm_80/sm_90 features (harness targets plain sm_100:
// no tcgen05 / no 'a'-suffix accelerated features available)
// ---------------------------------------------------------------------------
__device__ __forceinline__ uint32_t smem_u32(const void* p) {
    uint32_t a;
    asm("{ .reg .u64 t; cvta.to.shared.u64 t, %1; cvt.u32.u64 %0, t; }" : "=r"(a) : "l"(p));
    return a;
}
__device__ __forceinline__ void cp_async16(uint32_t saddr, const void* gptr) {
    asm volatile("cp.async.cg.shared.global [%0], [%1], 16;" :: "r"(saddr), "l"(gptr));
}
__device__ __forceinline__ void cp_commit() { asm volatile("cp.async.commit_group;"); }
template <int N>
__device__ __forceinline__ void cp_wait() { asm volatile("cp.async.wait_group %0;" :: "n"(N)); }

__device__ __forceinline__ void ldsm4(uint32_t& r0, uint32_t& r1, uint32_t& r2, uint32_t& r3,
                                      uint32_t addr) {
    asm volatile("ldmatrix.sync.aligned.m8n8.x4.shared.b16 {%0,%1,%2,%3}, [%4];"
                 : "=r"(r0), "=r"(r1), "=r"(r2), "=r"(r3) : "r"(addr));
}
__device__ __forceinline__ void mma16816(float* d, const uint32_t* a, uint32_t b0, uint32_t b1) {
    asm volatile(
        "mma.sync.aligned.m16n8k16.row.col.f32.f16.f16.f32 "
        "{%0,%1,%2,%3}, {%4,%5,%6,%7}, {%8,%9}, {%0,%1,%2,%3};"
        : "+f"(d[0]), "+f"(d[1]), "+f"(d[2]), "+f"(d[3])
        : "r"(a[0]), "r"(a[1]), "r"(a[2]), "r"(a[3]), "r"(b0), "r"(b1));
}

// ---------------------------------------------------------------------------
// Prologue kernels: fp32 -> fp16 convert (+ transpose for weights)
// ---------------------------------------------------------------------------
__global__ void cvt_x_kernel(const float* __restrict__ in, int n) {
    int i = (blockIdx.x * blockDim.x + threadIdx.x) * 4;
    if (i < n) {
        float4 v = *reinterpret_cast<const float4*>(in + i);
        *reinterpret_cast<__half2*>(g_xh + i)     = __floats2half2_rn(v.x, v.y);
        *reinterpret_cast<__half2*>(g_xh + i + 2) = __floats2half2_rn(v.z, v.w);
    }
}
// in [R, C] fp32 -> out [C, R] fp16  (which: 0 -> g_w1t, 1 -> g_w2t)
__global__ void tpose_cvt_kernel(const float* __restrict__ in, int R, int C, int which) {
    __shared__ float t[32][33];
    int c0 = blockIdx.x * 32, r0 = blockIdx.y * 32;
#pragma unroll
    for (int i = 0; i < 32; i += 8)
        t[threadIdx.y + i][threadIdx.x] =
            in[(size_t)(r0 + threadIdx.y + i) * C + c0 + threadIdx.x];
    __syncthreads();
    __half* out = which ? g_w2t : g_w1t;
#pragma unroll
    for (int i = 0; i < 32; i += 8)
        out[(size_t)(c0 + threadIdx.y + i) * R + r0 + threadIdx.x] =
            __float2half(t[threadIdx.x][threadIdx.y + i]);
}

// ---------------------------------------------------------------------------
// Pipelined HMMA GEMM: C[M,N] = A[M,K] @ B[N,K]^T, fp16 in, fp32 accum.
// CTA tile 128x128, BK=32, 4 cp.async stages, 256 threads (2x4 warps, 64x32/warp).
// MODE 0: +bias, relu -> fp16 g_h.   MODE 1: +bias, padding mask -> fp32 out.
// ---------------------------------------------------------------------------
static constexpr int BM = 128, BN = 128, BK = 32, STAGES = 4;
static constexpr int A_ST_BYTES = BM * BK * 2;   // 8192
static constexpr int B_ST_BYTES = BN * BK * 2;   // 8192
static constexpr int SMEM_TOTAL = STAGES * (A_ST_BYTES + B_ST_BYTES);  // 65536

// SMEM tile layout: row r (64B of fp16), 4 chunks of 16B; chunk c stored at
// c ^ ((r>>1)&3).  Conflict-free for cp.async stores and ldmatrix 8-lane phases.
__device__ __forceinline__ uint32_t sw_off(int r, int c) {
    return (uint32_t)(r * 64 + ((c ^ ((r >> 1) & 3)) << 4));
}

template <int MODE>
__global__ void __launch_bounds__(256)
ffn_gemm(const float* __restrict__ bias, const int* __restrict__ pad,
         float* __restrict__ outf, int Mtot, int K, int Ntot) {
    extern __shared__ __align__(1024) char smem[];
    const __half* __restrict__ Aptr = (MODE == 0) ? g_xh  : g_h;
    const __half* __restrict__ Bptr = (MODE == 0) ? g_w1t : g_w2t;

    const uint32_t smem_base = smem_u32(smem);
    const int tid  = threadIdx.x;
    const int lane = tid & 31, wid = tid >> 5;
    const int wm = wid >> 2;        // 0..1  -> 64-row slab
    const int wn = wid & 3;         // 0..3  -> 32-col slab
    const int m0 = blockIdx.y * BM;
    const int n0 = blockIdx.x * BN;
    const int KT = K / BK;

    const char* Abase = reinterpret_cast<const char*>(Aptr + (size_t)m0 * K);
    const char* Bbase = reinterpret_cast<const char*>(Bptr + (size_t)n0 * K);

    auto load_tile = [&](int kt, int s) {
        const uint32_t sA = smem_base + s * A_ST_BYTES;
        const uint32_t sB = smem_base + STAGES * A_ST_BYTES + s * B_ST_BYTES;
        const size_t koff = (size_t)kt * BK * 2;  // bytes into each row
#pragma unroll
        for (int i = 0; i < 2; ++i) {
            int idx = tid + i * 256;          // 512 chunks
            int r = idx >> 2, c = idx & 3;
            cp_async16(sA + sw_off(r, c), Abase + (size_t)r * K * 2 + koff + c * 16);
        }
#pragma unroll
        for (int i = 0; i < 2; ++i) {
            int idx = tid + i * 256;
            int r = idx >> 2, c = idx & 3;
            cp_async16(sB + sw_off(r, c), Bbase + (size_t)r * K * 2 + koff + c * 16);
        }
    };

    float acc[4][4][4];
#pragma unroll
    for (int i = 0; i < 4; ++i)
#pragma unroll
        for (int j = 0; j < 4; ++j)
#pragma unroll
            for (int q = 0; q < 4; ++q) acc[i][j][q] = 0.0f;

    // prologue: fill STAGES-1 stages
#pragma unroll
    for (int s = 0; s < STAGES - 1; ++s) { load_tile(s, s); cp_commit(); }

    for (int kt = 0; kt < KT; ++kt) {
        cp_wait<STAGES - 2>();
        __syncthreads();

        // issue next load first (overwrites stage read in iteration kt-1; safe after barrier)
        int nxt = kt + STAGES - 1;
        if (nxt < KT) load_tile(nxt, nxt & (STAGES - 1));
        cp_commit();

        const int s = kt & (STAGES - 1);
        const uint32_t sA = smem_base + s * A_ST_BYTES;
        const uint32_t sB = smem_base + STAGES * A_ST_BYTES + s * B_ST_BYTES;

#pragma unroll
        for (int kk = 0; kk < 2; ++kk) {  // two k16 halves of BK=32
            uint32_t a[4][4];
            {
                const int arow0 = wm * 64 + (lane & 15);
                const int ac = kk * 2 + (lane >> 4);
#pragma unroll
                for (int mt = 0; mt < 4; ++mt) {
                    int r = arow0 + mt * 16;
                    ldsm4(a[mt][0], a[mt][1], a[mt][2], a[mt][3], sA + sw_off(r, ac));
                }
            }
            uint32_t b[2][4];
            {
                const int g = lane >> 3, gr = lane & 7;
                const int bc = kk * 2 + (g & 1);
#pragma unroll
                for (int p = 0; p < 2; ++p) {
                    int nr = wn * 32 + p * 16 + ((g >> 1) << 3) + gr;
                    ldsm4(b[p][0], b[p][1], b[p][2], b[p][3], sB + sw_off(nr, bc));
                }
            }
#pragma unroll
            for (int mt = 0; mt < 4; ++mt)
#pragma unroll
                for (int nt = 0; nt < 4; ++nt)
                    mma16816(acc[mt][nt], a[mt], b[nt >> 1][(nt & 1) * 2],
                             b[nt >> 1][(nt & 1) * 2 + 1]);
        }
    }
    cp_wait<0>();

    // ------------------- epilogue -------------------
    const int quad = lane >> 2, qid = lane & 3;
#pragma unroll
    for (int mt = 0; mt < 4; ++mt) {
        const int mA = m0 + wm * 64 + mt * 16 + quad;   // rows mA and mA+8
        float s0 = 1.0f, s1 = 1.0f;
        if (MODE == 1) {
            s0 = (pad[mA] == 0) ? 1.0f : 0.0f;
            s1 = (pad[mA + 8] == 0) ? 1.0f : 0.0f;
        }
#pragma unroll
        for (int nt = 0; nt < 4; ++nt) {
            const int n = n0 + wn * 32 + nt * 8 + qid * 2;
            const float2 bb = *reinterpret_cast<const float2*>(bias + n);
            float d0 = acc[mt][nt][0] + bb.x, d1 = acc[mt][nt][1] + bb.y;
            float d2 = acc[mt][nt][2] + bb.x, d3 = acc[mt][nt][3] + bb.y;
            if (MODE == 0) {
                *reinterpret_cast<__half2*>(g_h + (size_t)mA * Ntot + n) =
                    __floats2half2_rn(fmaxf(d0, 0.0f), fmaxf(d1, 0.0f));
                *reinterpret_cast<__half2*>(g_h + (size_t)(mA + 8) * Ntot + n) =
                    __floats2half2_rn(fmaxf(d2, 0.0f), fmaxf(d3, 0.0f));
            } else {
                *reinterpret_cast<float2*>(outf + (size_t)mA * Ntot + n) =
                    make_float2(d0 * s0, d1 * s0);
                *reinterpret_cast<float2*>(outf + (size_t)(mA + 8) * Ntot + n) =
                    make_float2(d2 * s1, d3 * s1);
            }
        }
    }
}

// ---------------------------------------------------------------------------
// kernel_launch
// inputs: x[B,L,H] f32, padding[B,L] i32, W1[H,F] f32, b1[F] f32,
//         W2[F,H] f32, b2[H] f32  ->  out[B,L,H] f32
// ---------------------------------------------------------------------------
extern "C" void kernel_launch(void* const* d_in, const int* in_sizes, int n_in,
                              void* d_out, int out_size) {
    const float* x   = (const float*)d_in[0];
    const int*   pad = (const int*)d_in[1];
    const float* W1  = (const float*)d_in[2];
    const float* b1  = (const float*)d_in[3];
    const float* W2  = (const float*)d_in[4];
    const float* b2  = (const float*)d_in[5];
    float* out = (float*)d_out;

    const int Mtot = M_TOT, H = H_DIM, F = F_DIM;

    cudaFuncSetAttribute(ffn_gemm<0>, cudaFuncAttributeMaxDynamicSharedMemorySize, SMEM_TOTAL);
    cudaFuncSetAttribute(ffn_gemm<1>, cudaFuncAttributeMaxDynamicSharedMemorySize, SMEM_TOTAL);

    cvt_x_kernel<<<(Mtot * H / 4 + 255) / 256, 256>>>(x, Mtot * H);
    dim3 tb(32, 8);
    tpose_cvt_kernel<<<dim3(F / 32, H / 32), tb>>>(W1, H, F, 0);
    tpose_cvt_kernel<<<dim3(H / 32, F / 32), tb>>>(W2, F, H, 1);

    // GEMM1: h = relu(x @ W1 + b1)  [M, F] fp16
    ffn_gemm<0><<<dim3(F / BN, Mtot / BM), 256, SMEM_TOTAL>>>(b1, nullptr, nullptr, Mtot, H, F);
    // GEMM2: out = mask * (h @ W2 + b2)  [M, H] fp32
    ffn_gemm<1><<<dim3(H / BN, Mtot / BM), 256, SMEM_TOTAL>>>(b2, pad, out, Mtot, F, H);
}

// round 3
// speedup vs baseline: 1.1098x; 1.1098x over previous
#include <cuda_runtime.h>
#include <cuda_fp16.h>
#include <cstdint>

// ---------------------------------------------------------------------------
// Problem shape (fixed): B=4, L=4096, H=1024, F=4096
// ---------------------------------------------------------------------------
static constexpr int M_TOT = 16384;
static constexpr int H_DIM = 1024;
static constexpr int F_DIM = 4096;

__device__ __align__(16) __half g_xh [(size_t)M_TOT * H_DIM];  // x    fp16 [M, H]
__device__ __align__(16) __half g_w1t[(size_t)F_DIM * H_DIM];  // W1^T fp16 [F, H]
__device__ __align__(16) __half g_w2t[(size_t)H_DIM * F_DIM];  // W2^T fp16 [H, F]
__device__ __align__(16) __half g_h  [(size_t)M_TOT * F_DIM];  // relu(xW1+b1) [M, F]

// ---------------------------------------------------------------------------
// Portable sm_80/90 PTX helpers (harness targets plain sm_100 — no tcgen05)
// ---------------------------------------------------------------------------
__device__ __forceinline__ uint32_t smem_u32(const void* p) {
    uint32_t a;
    asm("{ .reg .u64 t; cvta.to.shared.u64 t, %1; cvt.u32.u64 %0, t; }" : "=r"(a) : "l"(p));
    return a;
}
__device__ __forceinline__ void cp_async16(uint32_t saddr, const void* gptr) {
    asm volatile("cp.async.cg.shared.global [%0], [%1], 16;" :: "r"(saddr), "l"(gptr));
}
__device__ __forceinline__ void cp_commit() { asm volatile("cp.async.commit_group;"); }
template <int N>
__device__ __forceinline__ void cp_wait() { asm volatile("cp.async.wait_group %0;" :: "n"(N)); }

__device__ __forceinline__ void ldsm4(uint32_t& r0, uint32_t& r1, uint32_t& r2, uint32_t& r3,
                                      uint32_t addr) {
    asm volatile("ldmatrix.sync.aligned.m8n8.x4.shared.b16 {%0,%1,%2,%3}, [%4];"
                 : "=r"(r0), "=r"(r1), "=r"(r2), "=r"(r3) : "r"(addr));
}
__device__ __forceinline__ void mma16816(float* d, const uint32_t* a, uint32_t b0, uint32_t b1) {
    asm volatile(
        "mma.sync.aligned.m16n8k16.row.col.f32.f16.f16.f32 "
        "{%0,%1,%2,%3}, {%4,%5,%6,%7}, {%8,%9}, {%0,%1,%2,%3};"
        : "+f"(d[0]), "+f"(d[1]), "+f"(d[2]), "+f"(d[3])
        : "r"(a[0]), "r"(a[1]), "r"(a[2]), "r"(a[3]), "r"(b0), "r"(b1));
}

// ---------------------------------------------------------------------------
// Prologue: fp32 -> fp16 convert (+ transpose for weights)
// ---------------------------------------------------------------------------
__global__ void cvt_x_kernel(const float* __restrict__ in, int n) {
    int i = (blockIdx.x * blockDim.x + threadIdx.x) * 4;
    if (i < n) {
        float4 v = *reinterpret_cast<const float4*>(in + i);
        *reinterpret_cast<__half2*>(g_xh + i)     = __floats2half2_rn(v.x, v.y);
        *reinterpret_cast<__half2*>(g_xh + i + 2) = __floats2half2_rn(v.z, v.w);
    }
}
__global__ void tpose_cvt_kernel(const float* __restrict__ in, int R, int C, int which) {
    __shared__ float t[32][33];
    int c0 = blockIdx.x * 32, r0 = blockIdx.y * 32;
#pragma unroll
    for (int i = 0; i < 32; i += 8)
        t[threadIdx.y + i][threadIdx.x] =
            in[(size_t)(r0 + threadIdx.y + i) * C + c0 + threadIdx.x];
    __syncthreads();
    __half* out = which ? g_w2t : g_w1t;
#pragma unroll
    for (int i = 0; i < 32; i += 8)
        out[(size_t)(c0 + threadIdx.y + i) * R + r0 + threadIdx.x] =
            __float2half(t[threadIdx.x][threadIdx.y + i]);
}

// ---------------------------------------------------------------------------
// Pipelined HMMA GEMM: C[M,N] = A[M,K] @ B[N,K]^T, fp16 in, fp32 accum.
// CTA 128x128, BK=64, 3 cp.async stages, 256 thr (2x4 warps, 64x32/warp).
// Register double-buffered ldmatrix fragments across k16 sub-steps.
// MODE 0: +bias, relu -> fp16 g_h.   MODE 1: +bias, padding mask -> fp32 out.
// ---------------------------------------------------------------------------
static constexpr int BM = 128, BN = 128, BK = 64, STAGES = 3;
static constexpr int A_ST_BYTES = BM * BK * 2;   // 16384
static constexpr int B_ST_BYTES = BN * BK * 2;   // 16384
static constexpr int SMEM_TOTAL = STAGES * (A_ST_BYTES + B_ST_BYTES);  // 98304

// Row = 128B (8 x 16B chunks); chunk c of row r stored at c ^ (r & 7).
// Conflict-free for cp.async 16B stores (one row per 8-lane phase) and for
// ldmatrix (8 rows, fixed c per phase -> 8 distinct chunks).
__device__ __forceinline__ uint32_t sw_off(int r, int c) {
    return (uint32_t)(r * 128 + ((c ^ (r & 7)) << 4));
}

template <int MODE>
__global__ void __launch_bounds__(256, 2)
ffn_gemm(const float* __restrict__ bias, const int* __restrict__ pad,
         float* __restrict__ outf, int Mtot, int K, int Ntot) {
    extern __shared__ __align__(1024) char smem[];
    const __half* __restrict__ Aptr = (MODE == 0) ? g_xh  : g_h;
    const __half* __restrict__ Bptr = (MODE == 0) ? g_w1t : g_w2t;

    const uint32_t smem_base = smem_u32(smem);
    const int tid  = threadIdx.x;
    const int lane = tid & 31, wid = tid >> 5;
    const int wm = wid >> 2;   // 0..1 -> 64-row slab
    const int wn = wid & 3;    // 0..3 -> 32-col slab
    const int m0 = blockIdx.y * BM;
    const int n0 = blockIdx.x * BN;
    const int KT = K / BK;

    const char* Abase = reinterpret_cast<const char*>(Aptr + (size_t)m0 * K);
    const char* Bbase = reinterpret_cast<const char*>(Bptr + (size_t)n0 * K);

    auto load_tile = [&](int kt, int s) {
        const uint32_t sA = smem_base + s * A_ST_BYTES;
        const uint32_t sB = smem_base + STAGES * A_ST_BYTES + s * B_ST_BYTES;
        const size_t koff = (size_t)kt * (BK * 2);
#pragma unroll
        for (int i = 0; i < 4; ++i) {  // 1024 chunks of A
            int idx = tid + i * 256;
            int r = idx >> 3, c = idx & 7;
            cp_async16(sA + sw_off(r, c), Abase + (size_t)r * K * 2 + koff + c * 16);
        }
#pragma unroll
        for (int i = 0; i < 4; ++i) {  // 1024 chunks of B
            int idx = tid + i * 256;
            int r = idx >> 3, c = idx & 7;
            cp_async16(sB + sw_off(r, c), Bbase + (size_t)r * K * 2 + koff + c * 16);
        }
    };

    // precomputed ldmatrix lane geometry
    const int a_row0 = wm * 64 + (lane & 15);
    const int a_chalf = lane >> 4;                       // which 16B within k16
    const int g = lane >> 3, gr = lane & 7;
    const int b_nr0 = wn * 32 + ((g >> 1) << 3) + gr;
    const int b_chalf = g & 1;

    float acc[4][4][4];
#pragma unroll
    for (int i = 0; i < 4; ++i)
#pragma unroll
        for (int j = 0; j < 4; ++j)
#pragma unroll
            for (int q = 0; q < 4; ++q) acc[i][j][q] = 0.0f;

    uint32_t af[2][4][4];  // [buf][mt][frag]
    uint32_t bf[2][2][4];  // [buf][p][frag]

    // prologue: fill STAGES-1 stages
#pragma unroll
    for (int s = 0; s < STAGES - 1; ++s) { load_tile(s, s); cp_commit(); }

    int s_cmp = 0, s_load = STAGES - 1;
    for (int kt = 0; kt < KT; ++kt) {
        cp_wait<STAGES - 2>();
        __syncthreads();

        if (kt + STAGES - 1 < KT) load_tile(kt + STAGES - 1, s_load);
        cp_commit();
        s_load = (s_load + 1 == STAGES) ? 0 : s_load + 1;

        const uint32_t sA = smem_base + s_cmp * A_ST_BYTES;
        const uint32_t sB = smem_base + STAGES * A_ST_BYTES + s_cmp * B_ST_BYTES;
        s_cmp = (s_cmp + 1 == STAGES) ? 0 : s_cmp + 1;

        // load fragments for kk = 0 into buffer 0
#pragma unroll
        for (int mt = 0; mt < 4; ++mt)
            ldsm4(af[0][mt][0], af[0][mt][1], af[0][mt][2], af[0][mt][3],
                  sA + sw_off(a_row0 + mt * 16, a_chalf));
#pragma unroll
        for (int p = 0; p < 2; ++p)
            ldsm4(bf[0][p][0], bf[0][p][1], bf[0][p][2], bf[0][p][3],
                  sB + sw_off(b_nr0 + p * 16, b_chalf));

#pragma unroll
        for (int kk = 0; kk < BK / 16; ++kk) {  // 4 k16 sub-steps
            const int cur = kk & 1, nxt = cur ^ 1;
            if (kk + 1 < BK / 16) {  // prefetch kk+1 fragments while MMAs run
                const int ac = (kk + 1) * 2 + a_chalf;
                const int bc = (kk + 1) * 2 + b_chalf;
#pragma unroll
                for (int mt = 0; mt < 4; ++mt)
                    ldsm4(af[nxt][mt][0], af[nxt][mt][1], af[nxt][mt][2], af[nxt][mt][3],
                          sA + sw_off(a_row0 + mt * 16, ac));
#pragma unroll
                for (int p = 0; p < 2; ++p)
                    ldsm4(bf[nxt][p][0], bf[nxt][p][1], bf[nxt][p][2], bf[nxt][p][3],
                          sB + sw_off(b_nr0 + p * 16, bc));
            }
#pragma unroll
            for (int mt = 0; mt < 4; ++mt)
#pragma unroll
                for (int nt = 0; nt < 4; ++nt)
                    mma16816(acc[mt][nt], af[cur][mt],
                             bf[cur][nt >> 1][(nt & 1) * 2],
                             bf[cur][nt >> 1][(nt & 1) * 2 + 1]);
        }
    }
    cp_wait<0>();

    // ------------------- epilogue -------------------
    const int quad = lane >> 2, qid = lane & 3;
#pragma unroll
    for (int mt = 0; mt < 4; ++mt) {
        const int mA = m0 + wm * 64 + mt * 16 + quad;   // rows mA and mA+8
        float s0 = 1.0f, s1 = 1.0f;
        if (MODE == 1) {
            s0 = (pad[mA] == 0) ? 1.0f : 0.0f;
            s1 = (pad[mA + 8] == 0) ? 1.0f : 0.0f;
        }
#pragma unroll
        for (int nt = 0; nt < 4; ++nt) {
            const int n = n0 + wn * 32 + nt * 8 + qid * 2;
            const float2 bb = *reinterpret_cast<const float2*>(bias + n);
            float d0 = acc[mt][nt][0] + bb.x, d1 = acc[mt][nt][1] + bb.y;
            float d2 = acc[mt][nt][2] + bb.x, d3 = acc[mt][nt][3] + bb.y;
            if (MODE == 0) {
                *reinterpret_cast<__half2*>(g_h + (size_t)mA * Ntot + n) =
                    __floats2half2_rn(fmaxf(d0, 0.0f), fmaxf(d1, 0.0f));
                *reinterpret_cast<__half2*>(g_h + (size_t)(mA + 8) * Ntot + n) =
                    __floats2half2_rn(fmaxf(d2, 0.0f), fmaxf(d3, 0.0f));
            } else {
                *reinterpret_cast<float2*>(outf + (size_t)mA * Ntot + n) =
                    make_float2(d0 * s0, d1 * s0);
                *reinterpret_cast<float2*>(outf + (size_t)(mA + 8) * Ntot + n) =
                    make_float2(d2 * s1, d3 * s1);
            }
        }
    }
}

// ---------------------------------------------------------------------------
// kernel_launch — inputs: x f32, padding i32, W1 f32, b1 f32, W2 f32, b2 f32
// ---------------------------------------------------------------------------
extern "C" void kernel_launch(void* const* d_in, const int* in_sizes, int n_in,
                              void* d_out, int out_size) {
    const float* x   = (const float*)d_in[0];
    const int*   pad = (const int*)d_in[1];
    const float* W1  = (const float*)d_in[2];
    const float* b1  = (const float*)d_in[3];
    const float* W2  = (const float*)d_in[4];
    const float* b2  = (const float*)d_in[5];
    float* out = (float*)d_out;

    const int Mtot = M_TOT, H = H_DIM, F = F_DIM;

    cudaFuncSetAttribute(ffn_gemm<0>, cudaFuncAttributeMaxDynamicSharedMemorySize, SMEM_TOTAL);
    cudaFuncSetAttribute(ffn_gemm<1>, cudaFuncAttributeMaxDynamicSharedMemorySize, SMEM_TOTAL);

    cvt_x_kernel<<<(Mtot * H / 4 + 255) / 256, 256>>>(x, Mtot * H);
    dim3 tb(32, 8);
    tpose_cvt_kernel<<<dim3(F / 32, H / 32), tb>>>(W1, H, F, 0);
    tpose_cvt_kernel<<<dim3(H / 32, F / 32), tb>>>(W2, F, H, 1);

    ffn_gemm<0><<<dim3(F / BN, Mtot / BM), 256, SMEM_TOTAL>>>(b1, nullptr, nullptr, Mtot, H, F);
    ffn_gemm<1><<<dim3(H / BN, Mtot / BM), 256, SMEM_TOTAL>>>(b2, pad, out, Mtot, F, H);
}